// round 16
// baseline (speedup 1.0000x reference)
#include <cuda_runtime.h>
#include <cuda_fp16.h>

// Phase vocoder time-stretch, rate = 0.9, phase_advance = 0.
// out[t] = mag[t] * U[t],  U[t] = prod_{k<=t} z[k]
//   z[0]   = s[0]/|s[0]|          (stored in spare table slot 2303)
//   z[t>0] = r[jm(t-1)],  r[j] = normalize(s[j+1]*conj(s[j]))
//   mag[t] = n0 + a*(n1-n0),  (n0,n1) = npair[jm] (fp16 pair), jm=floor(t*0.9f)
// Rotations stay fp32 (phase error would random-walk through the cumprod).
// Norm pairs + output staging in fp16: combined deterministic rel err
// ~4.5e-4 worst case, under the 1e-3 gate with margin.
// Epilogue reads 2 staged half2 per LDS.64 and stores float4 (half the instrs).

constexpr int Bb      = 16;
constexpr int Fb      = 1025;
constexpr int T       = 2048;
constexpr int TOUT    = 2276;          // ceil(2048 / 0.9)
constexpr int THREADS = 256;
constexpr int PER     = 9;             // 256 * 9 = 2304 >= 2276
constexpr float RATE  = 0.9f;

constexpr long long N_CPLX = (long long)Bb * Fb * TOUT;   // 37,326,400

constexpr int Z0SLOT = 2303;           // padi stores reach 2302; identity ext starts 2304
constexpr int TBL    = 2336;           // covers padi(2073) = 2332
// pool: rrs (fp32, TBL) + ris (fp32, TBL) + npair (half2, TBL)
constexpr int POOL_BYTES = TBL * 4 * 2 + TBL * 4;

__device__ __forceinline__ int padi(int j) { return j + (j >> 3); }

__device__ __forceinline__ float sqrt_approx(float x) {
    float r;
    asm("sqrt.approx.f32 %0, %1;" : "=f"(r) : "f"(x));
    return r;
}

__global__ __launch_bounds__(THREADS, 6) void pv_kernel(
    const float* __restrict__ xr, const float* __restrict__ xi,
    float* __restrict__ out, int writeMode)
{
    __shared__ __align__(16) unsigned char pool[POOL_BYTES];
    __shared__ __align__(16) float2 cf[THREADS + 1];
    __shared__ float2 wscan[THREADS / 32];

    float*   const rrs   = (float*)pool;                  // padded SoA rot.re (fp32)
    float*   const ris   = (float*)(pool + TBL * 4);      // padded SoA rot.im (fp32)
    __half2* const npair = (__half2*)(pool + TBL * 8);    // padded (|s[j]|,|s[j+1]|) fp16
    __half2* const ob    = (__half2*)pool;                // staging aliases pool (2304)

    const int row = blockIdx.x;
    const float4* __restrict__ r4 = (const float4*)(xr + (size_t)row * T);
    const float4* __restrict__ i4 = (const float4*)(xi + (size_t)row * T);
    const int tid  = threadIdx.x;
    const int lane = tid & 31;
    const int warp = tid >> 5;

    // ---- load 8 contiguous j per thread + boundary exchange ----
    float4 ar0 = r4[2 * tid], ar1 = r4[2 * tid + 1];
    float4 ai0 = i4[2 * tid], ai1 = i4[2 * tid + 1];
    cf[tid] = make_float2(ar0.x, ai0.x);                // s[8*tid]
    if (tid == 0) cf[THREADS] = make_float2(0.f, 0.f);  // s[2048] = 0 (zero pad)

    // ---- precompute (pre-barrier part): needs only own registers ----
    float sx[8], sy[8];
    sx[0] = ar0.x; sx[1] = ar0.y; sx[2] = ar0.z; sx[3] = ar0.w;
    sx[4] = ar1.x; sx[5] = ar1.y; sx[6] = ar1.z; sx[7] = ar1.w;
    sy[0] = ai0.x; sy[1] = ai0.y; sy[2] = ai0.z; sy[3] = ai0.w;
    sy[4] = ai1.x; sy[5] = ai1.y; sy[6] = ai1.z; sy[7] = ai1.w;

    const int base = 9 * tid;           // == padi(8*tid + q) - q
    float nm[8];
    #pragma unroll
    for (int q = 0; q < 8; q++)
        nm[q] = sqrt_approx(sx[q] * sx[q] + sy[q] * sy[q]);
    #pragma unroll
    for (int q = 0; q < 7; q++)
        npair[base + q] = __floats2half2_rn(nm[q], nm[q+1]);

    #pragma unroll
    for (int q = 0; q < 7; q++) {       // rotations using own data only
        float pr = sx[q+1] * sx[q] + sy[q+1] * sy[q];   // s[j+1] * conj(s[j])
        float pq = sy[q+1] * sx[q] - sx[q+1] * sy[q];
        float inv = rsqrtf(pr * pr + pq * pq);
        rrs[base + q] = pr * inv;
        ris[base + q] = pq * inv;
    }
    if (tid == 0) {                                     // z0 in spare slot
        float n2 = sx[0] * sx[0] + sy[0] * sy[0];
        float zx, zy;
        if (n2 > 0.f) { float inv = rsqrtf(n2); zx = sx[0] * inv; zy = sy[0] * inv; }
        else          { zx = 1.f; zy = 0.f; }
        rrs[Z0SLOT] = zx; ris[Z0SLOT] = zy;
    }
    if (tid < 26) {                                     // identity tail j=2048..2073
        int jp = padi(2048 + tid);
        rrs[jp] = 1.f; ris[jp] = 0.f;
        npair[jp] = __floats2half2_rn(0.f, 0.f);
    }
    __syncthreads();                                    // cf[] ready

    // ---- q = 7 rotation + npair (needs neighbor's first element) ----
    {
        float2 nx = cf[tid + 1];
        float nm8 = sqrt_approx(nx.x * nx.x + nx.y * nx.y);
        npair[base + 7] = __floats2half2_rn(nm[7], nm8);
        float pr = nx.x * sx[7] + nx.y * sy[7];
        float pq = nx.y * sx[7] - nx.x * sy[7];
        float inv = rsqrtf(pr * pr + pq * pq);          // NaN only for tid==255
        float zx = pr * inv, zy = pq * inv;
        if (tid == 255) { zx = 1.f; zy = 0.f; }         // j=2047 pairs with zero pad
        rrs[base + 7] = zx;
        ris[base + 7] = zy;
    }
    __syncthreads();                                    // tables ready

    const int t0 = tid * PER;

    // ---- pass 1: branch-free gather (3 LDS.32), local product, premultiply ----
    float vr[PER], vi[PER];
    float ur = 1.f, ui = 0.f;
    float tf = (float)t0;                               // exact integer in fp32
    int pmold;                                          // z index; becomes prev pm
    if (t0 == 0) pmold = Z0SLOT;
    else { int jp = (int)((float)(t0 - 1) * RATE); pmold = jp + (jp >> 3); }
    #pragma unroll
    for (int k = 0; k < PER; k++) {
        float ts = tf * RATE;                           // == fl((float)t * 0.9f)
        int jm  = (int)ts;
        float al = ts - (float)jm;
        int pm  = jm + (jm >> 3);                       // padi(jm)

        float zx = rrs[pmold];                          // z(t) = rot[jm(t-1)] (or z0)
        float zy = ris[pmold];

        float2 nf = __half22float2(npair[pm]);          // (n0, n1)
        float mg = nf.x + al * (nf.y - nf.x);

        float nr = ur * zx - ui * zy;
        float ni = ur * zy + ui * zx;
        ur = nr; ui = ni;
        vr[k] = mg * ur; vi[k] = mg * ui;               // premultiplied local product

        pmold = pm;
        tf += 1.f;
    }

    // ---- block-wide inclusive scan (complex multiply) ----
    float pr = ur, pi = ui;
    #pragma unroll
    for (int off = 1; off < 32; off <<= 1) {
        float orr = __shfl_up_sync(0xFFFFFFFFu, pr, off);
        float oii = __shfl_up_sync(0xFFFFFFFFu, pi, off);
        if (lane >= off) {
            float tr = orr * pr - oii * pi;
            float ti = orr * pi + oii * pr;
            pr = tr; pi = ti;
        }
    }
    if (lane == 31) wscan[warp] = make_float2(pr, pi);
    __syncthreads();
    if (tid < (THREADS / 32)) {
        float ar = wscan[tid].x, ai = wscan[tid].y;
        #pragma unroll
        for (int off = 1; off < (THREADS / 32); off <<= 1) {
            float orr = __shfl_up_sync(0xFFu, ar, off);
            float oii = __shfl_up_sync(0xFFu, ai, off);
            if (tid >= off) {
                float tr = orr * ar - oii * ai;
                float ti = orr * ai + oii * ar;
                ar = tr; ai = ti;
            }
        }
        wscan[tid] = make_float2(ar, ai);
    }
    __syncthreads();

    // thread-exclusive prefix
    float exr = __shfl_up_sync(0xFFFFFFFFu, pr, 1);
    float exi = __shfl_up_sync(0xFFFFFFFFu, pi, 1);
    if (lane == 0) { exr = 1.f; exi = 0.f; }
    if (warp > 0) {
        float2 w = wscan[warp - 1];
        float tr = w.x * exr - w.y * exi;
        float ti = w.x * exi + w.y * exr;
        exr = tr; exi = ti;
    }
    {   // renormalize (|.| ~ 1)
        float n2 = exr * exr + exi * exi;
        float inv = rsqrtf(n2);
        exr *= inv; exi *= inv;
    }

    // ---- pass 2: 9 complex muls -> packed half2 staging (stride 9, CF) ----
    #pragma unroll
    for (int k = 0; k < PER; k++) {
        int t = t0 + k;
        float orv = exr * vr[k] - exi * vi[k];
        float oiv = exr * vi[k] + exi * vr[k];
        ob[t] = __floats2half2_rn(orv, oiv);
    }
    __syncthreads();

    // ---- epilogue: LDS.64 reads 2 outputs, STG.128 writes 2 outputs ----
    if (writeMode == 1) {
        float4* __restrict__ orow4 = (float4*)(out + (size_t)row * TOUT * 2);
        const uint2* ob2 = (const uint2*)ob;            // 2 half2 per entry
        #pragma unroll
        for (int it = 0; it < 4; it++) {
            int i = tid + it * THREADS;                 // max 1023 < 1138
            uint2 two = ob2[i];
            float2 va = __half22float2(*(const __half2*)&two.x);
            float2 vb = __half22float2(*(const __half2*)&two.y);
            orow4[i] = make_float4(va.x, va.y, vb.x, vb.y);
        }
        if (tid < (TOUT / 2) - 4 * THREADS) {           // tail: 114 threads
            int i = 4 * THREADS + tid;
            uint2 two = ob2[i];
            float2 va = __half22float2(*(const __half2*)&two.x);
            float2 vb = __half22float2(*(const __half2*)&two.y);
            orow4[i] = make_float4(va.x, va.y, vb.x, vb.y);
        }
    } else {
        float* __restrict__ orow = out + (size_t)row * TOUT;
        for (int i = tid; i < TOUT; i += THREADS) orow[i] = __half22float2(ob[i]).x;
    }
}

extern "C" void kernel_launch(void* const* d_in, const int* in_sizes, int n_in,
                              void* d_out, int out_size) {
    const float* xr = (const float*)d_in[0];
    const float* xi = (const float*)d_in[1];
    int writeMode = ((long long)out_size >= 2 * N_CPLX) ? 1 : 0;
    pv_kernel<<<Bb * Fb, THREADS>>>(xr, xi, (float*)d_out, writeMode);
}

// round 17
// speedup vs baseline: 1.0144x; 1.0144x over previous
#include <cuda_runtime.h>
#include <cuda_fp16.h>

// Phase vocoder time-stretch, rate = 0.9, phase_advance = 0.
// out[t] = mag[t] * U[t],  U[t] = prod_{k<=t} z[k]
//   z[0]   = s[0]/|s[0]|          (stored in spare table slot 2303)
//   z[t>0] = r[jm(t-1)],  r[j] = normalize(s[j+1]*conj(s[j]))
//   mag[t] = n0 + a*(n1-n0),  (n0,n1) = npair[jm] (fp16 pair), jm=floor(t*0.9f)
// Rotations fp32 (phase error would random-walk through the cumprod).
// Local products v[k] = mg*Uloc packed as half2 in REGISTERS (9 regs, not 18)
// -> regs ~33, enabling __launch_bounds__(256,7): 56 warps/SM to overlap the
// L1-phase floor. npair + staging remain fp16 (measured err ~2.7e-4).

constexpr int Bb      = 16;
constexpr int Fb      = 1025;
constexpr int T       = 2048;
constexpr int TOUT    = 2276;          // ceil(2048 / 0.9)
constexpr int THREADS = 256;
constexpr int PER     = 9;             // 256 * 9 = 2304 >= 2276
constexpr float RATE  = 0.9f;

constexpr long long N_CPLX = (long long)Bb * Fb * TOUT;   // 37,326,400

constexpr int Z0SLOT = 2303;           // padi stores reach 2302; identity ext starts 2304
constexpr int TBL    = 2336;           // covers padi(2073) = 2332
// pool: rrs (fp32, TBL) + ris (fp32, TBL) + npair (half2, TBL)
constexpr int POOL_BYTES = TBL * 4 * 2 + TBL * 4;

__device__ __forceinline__ int padi(int j) { return j + (j >> 3); }

__device__ __forceinline__ float sqrt_approx(float x) {
    float r;
    asm("sqrt.approx.f32 %0, %1;" : "=f"(r) : "f"(x));
    return r;
}

__global__ __launch_bounds__(THREADS, 7) void pv_kernel(
    const float* __restrict__ xr, const float* __restrict__ xi,
    float* __restrict__ out, int writeMode)
{
    __shared__ __align__(16) unsigned char pool[POOL_BYTES];
    __shared__ __align__(16) float2 cf[THREADS + 1];
    __shared__ float2 wscan[THREADS / 32];

    float*   const rrs   = (float*)pool;                  // padded SoA rot.re (fp32)
    float*   const ris   = (float*)(pool + TBL * 4);      // padded SoA rot.im (fp32)
    __half2* const npair = (__half2*)(pool + TBL * 8);    // padded (|s[j]|,|s[j+1]|) fp16
    __half2* const ob    = (__half2*)pool;                // staging aliases pool (2304)

    const int row = blockIdx.x;
    const float4* __restrict__ r4 = (const float4*)(xr + (size_t)row * T);
    const float4* __restrict__ i4 = (const float4*)(xi + (size_t)row * T);
    const int tid  = threadIdx.x;
    const int lane = tid & 31;
    const int warp = tid >> 5;

    // ---- load 8 contiguous j per thread + boundary exchange ----
    float4 ar0 = r4[2 * tid], ar1 = r4[2 * tid + 1];
    float4 ai0 = i4[2 * tid], ai1 = i4[2 * tid + 1];
    cf[tid] = make_float2(ar0.x, ai0.x);                // s[8*tid]
    if (tid == 0) cf[THREADS] = make_float2(0.f, 0.f);  // s[2048] = 0 (zero pad)

    // ---- precompute (pre-barrier part): needs only own registers ----
    float sx[8], sy[8];
    sx[0] = ar0.x; sx[1] = ar0.y; sx[2] = ar0.z; sx[3] = ar0.w;
    sx[4] = ar1.x; sx[5] = ar1.y; sx[6] = ar1.z; sx[7] = ar1.w;
    sy[0] = ai0.x; sy[1] = ai0.y; sy[2] = ai0.z; sy[3] = ai0.w;
    sy[4] = ai1.x; sy[5] = ai1.y; sy[6] = ai1.z; sy[7] = ai1.w;

    const int base = 9 * tid;           // == padi(8*tid + q) - q
    float nm[8];
    #pragma unroll
    for (int q = 0; q < 8; q++)
        nm[q] = sqrt_approx(sx[q] * sx[q] + sy[q] * sy[q]);
    #pragma unroll
    for (int q = 0; q < 7; q++)
        npair[base + q] = __floats2half2_rn(nm[q], nm[q+1]);

    #pragma unroll
    for (int q = 0; q < 7; q++) {       // rotations using own data only
        float pr = sx[q+1] * sx[q] + sy[q+1] * sy[q];   // s[j+1] * conj(s[j])
        float pq = sy[q+1] * sx[q] - sx[q+1] * sy[q];
        float inv = rsqrtf(pr * pr + pq * pq);
        rrs[base + q] = pr * inv;
        ris[base + q] = pq * inv;
    }
    if (tid == 0) {                                     // z0 in spare slot
        float n2 = sx[0] * sx[0] + sy[0] * sy[0];
        float zx, zy;
        if (n2 > 0.f) { float inv = rsqrtf(n2); zx = sx[0] * inv; zy = sy[0] * inv; }
        else          { zx = 1.f; zy = 0.f; }
        rrs[Z0SLOT] = zx; ris[Z0SLOT] = zy;
    }
    if (tid < 26) {                                     // identity tail j=2048..2073
        int jp = padi(2048 + tid);
        rrs[jp] = 1.f; ris[jp] = 0.f;
        npair[jp] = __floats2half2_rn(0.f, 0.f);
    }
    __syncthreads();                                    // cf[] ready

    // ---- q = 7 rotation + npair (needs neighbor's first element) ----
    {
        float2 nx = cf[tid + 1];
        float nm8 = sqrt_approx(nx.x * nx.x + nx.y * nx.y);
        npair[base + 7] = __floats2half2_rn(nm[7], nm8);
        float pr = nx.x * sx[7] + nx.y * sy[7];
        float pq = nx.y * sx[7] - nx.x * sy[7];
        float inv = rsqrtf(pr * pr + pq * pq);          // NaN only for tid==255
        float zx = pr * inv, zy = pq * inv;
        if (tid == 255) { zx = 1.f; zy = 0.f; }         // j=2047 pairs with zero pad
        rrs[base + 7] = zx;
        ris[base + 7] = zy;
    }
    __syncthreads();                                    // tables ready

    const int t0 = tid * PER;

    // ---- pass 1: branch-free gather (3 LDS.32), local product, pack v -> half2 ----
    unsigned int vp[PER];                               // packed (v.re, v.im), 9 regs
    float ur = 1.f, ui = 0.f;
    float tf = (float)t0;                               // exact integer in fp32
    int pmold;                                          // z index; becomes prev pm
    if (t0 == 0) pmold = Z0SLOT;
    else { int jp = (int)((float)(t0 - 1) * RATE); pmold = jp + (jp >> 3); }
    #pragma unroll
    for (int k = 0; k < PER; k++) {
        float ts = tf * RATE;                           // == fl((float)t * 0.9f)
        int jm  = (int)ts;
        float al = ts - (float)jm;
        int pm  = jm + (jm >> 3);                       // padi(jm)

        float zx = rrs[pmold];                          // z(t) = rot[jm(t-1)] (or z0)
        float zy = ris[pmold];

        float2 nf = __half22float2(npair[pm]);          // (n0, n1)
        float mg = nf.x + al * (nf.y - nf.x);

        float nr = ur * zx - ui * zy;
        float ni = ur * zy + ui * zx;
        ur = nr; ui = ni;
        __half2 h = __floats2half2_rn(mg * ur, mg * ui);
        vp[k] = *(unsigned int*)&h;                     // packed local product

        pmold = pm;
        tf += 1.f;
    }

    // ---- block-wide inclusive scan (complex multiply) ----
    float pr = ur, pi = ui;
    #pragma unroll
    for (int off = 1; off < 32; off <<= 1) {
        float orr = __shfl_up_sync(0xFFFFFFFFu, pr, off);
        float oii = __shfl_up_sync(0xFFFFFFFFu, pi, off);
        if (lane >= off) {
            float tr = orr * pr - oii * pi;
            float ti = orr * pi + oii * pr;
            pr = tr; pi = ti;
        }
    }
    if (lane == 31) wscan[warp] = make_float2(pr, pi);
    __syncthreads();
    if (tid < (THREADS / 32)) {
        float ar = wscan[tid].x, ai = wscan[tid].y;
        #pragma unroll
        for (int off = 1; off < (THREADS / 32); off <<= 1) {
            float orr = __shfl_up_sync(0xFFu, ar, off);
            float oii = __shfl_up_sync(0xFFu, ai, off);
            if (tid >= off) {
                float tr = orr * ar - oii * ai;
                float ti = orr * ai + oii * ar;
                ar = tr; ai = ti;
            }
        }
        wscan[tid] = make_float2(ar, ai);
    }
    __syncthreads();

    // thread-exclusive prefix
    float exr = __shfl_up_sync(0xFFFFFFFFu, pr, 1);
    float exi = __shfl_up_sync(0xFFFFFFFFu, pi, 1);
    if (lane == 0) { exr = 1.f; exi = 0.f; }
    if (warp > 0) {
        float2 w = wscan[warp - 1];
        float tr = w.x * exr - w.y * exi;
        float ti = w.x * exi + w.y * exr;
        exr = tr; exi = ti;
    }
    {   // renormalize (|.| ~ 1)
        float n2 = exr * exr + exi * exi;
        float inv = rsqrtf(n2);
        exr *= inv; exi *= inv;
    }

    // ---- pass 2: unpack v, apply prefix, repack -> half2 staging (stride 9, CF) ----
    #pragma unroll
    for (int k = 0; k < PER; k++) {
        int t = t0 + k;
        float2 v = __half22float2(*(__half2*)&vp[k]);
        float orv = exr * v.x - exi * v.y;
        float oiv = exr * v.y + exi * v.x;
        ob[t] = __floats2half2_rn(orv, oiv);
    }
    __syncthreads();

    // ---- epilogue: LDS.64 reads 2 outputs, STG.128 writes 2 outputs ----
    if (writeMode == 1) {
        float4* __restrict__ orow4 = (float4*)(out + (size_t)row * TOUT * 2);
        const uint2* ob2 = (const uint2*)ob;            // 2 half2 per entry
        #pragma unroll
        for (int it = 0; it < 4; it++) {
            int i = tid + it * THREADS;                 // max 1023 < 1138
            uint2 two = ob2[i];
            float2 va = __half22float2(*(const __half2*)&two.x);
            float2 vb = __half22float2(*(const __half2*)&two.y);
            orow4[i] = make_float4(va.x, va.y, vb.x, vb.y);
        }
        if (tid < (TOUT / 2) - 4 * THREADS) {           // tail: 114 threads
            int i = 4 * THREADS + tid;
            uint2 two = ob2[i];
            float2 va = __half22float2(*(const __half2*)&two.x);
            float2 vb = __half22float2(*(const __half2*)&two.y);
            orow4[i] = make_float4(va.x, va.y, vb.x, vb.y);
        }
    } else {
        float* __restrict__ orow = out + (size_t)row * TOUT;
        for (int i = tid; i < TOUT; i += THREADS) orow[i] = __half22float2(ob[i]).x;
    }
}

extern "C" void kernel_launch(void* const* d_in, const int* in_sizes, int n_in,
                              void* d_out, int out_size) {
    const float* xr = (const float*)d_in[0];
    const float* xi = (const float*)d_in[1];
    int writeMode = ((long long)out_size >= 2 * N_CPLX) ? 1 : 0;
    pv_kernel<<<Bb * Fb, THREADS>>>(xr, xi, (float*)d_out, writeMode);
}